// round 1
// baseline (speedup 1.0000x reference)
#include <cuda_runtime.h>
#include <cstdint>

#define NROWS 32768
#define KEMB  8192
#define DDIM  512

// Scratch (no cudaMalloc allowed): per-row packed (ordered_dist, idx) and ||e||^2
__device__ unsigned long long g_best[NROWS];
__device__ float g_enorm[KEMB];

// ---------------- packed f32x2 helpers (Blackwell FFMA2 via PTX) ----------------
__device__ __forceinline__ void fma2(unsigned long long& c, unsigned long long a,
                                     unsigned long long b) {
    asm("fma.rn.f32x2 %0, %1, %2, %3;" : "=l"(c) : "l"(a), "l"(b), "l"(c));
}
__device__ __forceinline__ float2 unpack2(unsigned long long v) {
    float2 f;
    asm("mov.b64 {%0, %1}, %2;" : "=f"(f.x), "=f"(f.y) : "l"(v));
    return f;
}
// Order-preserving fp32 -> uint32 (total order, min works for argmin)
__device__ __forceinline__ unsigned int ford(float f) {
    unsigned int u = __float_as_uint(f);
    return (u & 0x80000000u) ? ~u : (u | 0x80000000u);
}
__device__ __forceinline__ unsigned long long umin64(unsigned long long a,
                                                     unsigned long long b) {
    return a < b ? a : b;
}

// ---------------- kernel 1: reset argmin state ----------------
__global__ void init_best_kernel() {
    int i = blockIdx.x * blockDim.x + threadIdx.x;
    if (i < NROWS) g_best[i] = 0xFFFFFFFFFFFFFFFFull;
}

// ---------------- kernel 2: ||e_k||^2, one warp per code row ----------------
__global__ void enorm_kernel(const float* __restrict__ E) {
    int w = (blockIdx.x * blockDim.x + threadIdx.x) >> 5;
    int lane = threadIdx.x & 31;
    if (w >= KEMB) return;
    const float4* row = (const float4*)(E + (size_t)w * DDIM);
    float s = 0.f;
#pragma unroll
    for (int i = 0; i < 4; ++i) {
        float4 v = row[lane + 32 * i];
        s += v.x * v.x + v.y * v.y + v.z * v.z + v.w * v.w;
    }
#pragma unroll
    for (int o = 16; o > 0; o >>= 1) s += __shfl_xor_sync(0xffffffffu, s, o);
    if (lane == 0) g_enorm[w] = s;
}

// ---------------- kernel 3: tiled fp32 GEMM (FFMA2) + fused argmin ----------------
// Tile: 128 rows (x) x 128 cols (codes), k-step 16 over D=512.
// A stored DUPLICATED in smem so (a,a) pairs load directly as u64 (no pack movs).
#define AS_STRIDE 268   // 256 floats (128 dup pairs) + pad; %4==0 keeps 16B align
#define BS_STRIDE 132   // 128 floats + pad; %4==0

__global__ __launch_bounds__(256, 2) void vq_gemm_argmin(
    const float* __restrict__ X, const float* __restrict__ E) {
    __shared__ __align__(16) float As[16][AS_STRIDE];
    __shared__ __align__(16) float Bs[16][BS_STRIDE];
    __shared__ float en_s[128];

    const int ct = blockIdx.x;   // code (col) tile: 0..63
    const int rt = blockIdx.y;   // row tile: 0..255
    const int tid = threadIdx.x;
    const int tx = tid & 15;     // col group
    const int ty = tid >> 4;     // row group

    if (tid < 128) en_s[tid] = g_enorm[ct * 128 + tid];

    // Loader mapping: float4 slots f = tid and tid+256; row = f>>2, dseg = f&3
    const int r0 = tid >> 2, s0 = tid & 3;
    const int r1 = (tid + 256) >> 2, s1 = (tid + 256) & 3;
    const int d0 = s0 * 4, d1 = s1 * 4;

    const float* Ap0 = X + ((size_t)rt * 128 + r0) * DDIM + d0;
    const float* Ap1 = X + ((size_t)rt * 128 + r1) * DDIM + d1;
    const float* Bp0 = E + ((size_t)ct * 128 + r0) * DDIM + d0;
    const float* Bp1 = E + ((size_t)ct * 128 + r1) * DDIM + d1;

    unsigned long long c2[8][4];
#pragma unroll
    for (int i = 0; i < 8; ++i)
#pragma unroll
        for (int p = 0; p < 4; ++p) c2[i][p] = 0ull;

    // register prefetch of tile 0
    float4 va0 = *(const float4*)Ap0;
    float4 va1 = *(const float4*)Ap1;
    float4 vb0 = *(const float4*)Bp0;
    float4 vb1 = *(const float4*)Bp1;

    for (int kt = 0; kt < 32; ++kt) {
        // stage regs -> smem (A duplicated pairs, transposed to [d][n])
        *(float2*)&As[d0 + 0][2 * r0] = make_float2(va0.x, va0.x);
        *(float2*)&As[d0 + 1][2 * r0] = make_float2(va0.y, va0.y);
        *(float2*)&As[d0 + 2][2 * r0] = make_float2(va0.z, va0.z);
        *(float2*)&As[d0 + 3][2 * r0] = make_float2(va0.w, va0.w);
        *(float2*)&As[d1 + 0][2 * r1] = make_float2(va1.x, va1.x);
        *(float2*)&As[d1 + 1][2 * r1] = make_float2(va1.y, va1.y);
        *(float2*)&As[d1 + 2][2 * r1] = make_float2(va1.z, va1.z);
        *(float2*)&As[d1 + 3][2 * r1] = make_float2(va1.w, va1.w);
        Bs[d0 + 0][r0] = vb0.x;
        Bs[d0 + 1][r0] = vb0.y;
        Bs[d0 + 2][r0] = vb0.z;
        Bs[d0 + 3][r0] = vb0.w;
        Bs[d1 + 0][r1] = vb1.x;
        Bs[d1 + 1][r1] = vb1.y;
        Bs[d1 + 2][r1] = vb1.z;
        Bs[d1 + 3][r1] = vb1.w;
        __syncthreads();

        if (kt < 31) {  // prefetch next k-tile while computing this one
            va0 = *(const float4*)(Ap0 + (kt + 1) * 16);
            va1 = *(const float4*)(Ap1 + (kt + 1) * 16);
            vb0 = *(const float4*)(Bp0 + (kt + 1) * 16);
            vb1 = *(const float4*)(Bp1 + (kt + 1) * 16);
        }

#pragma unroll
        for (int d = 0; d < 16; ++d) {
            const ulonglong2* Ad = (const ulonglong2*)&As[d][0];
            const ulonglong2* Bd = (const ulonglong2*)&Bs[d][0];
            // rows 4ty..4ty+3 and 64+4ty..64+4ty+3 as duplicated (a,a) pairs
            ulonglong2 a01 = Ad[2 * ty];
            ulonglong2 a23 = Ad[2 * ty + 1];
            ulonglong2 a45 = Ad[32 + 2 * ty];
            ulonglong2 a67 = Ad[32 + 2 * ty + 1];
            // cols 4tx..4tx+3 and 64+4tx..64+4tx+3 as adjacent (b0,b1) pairs
            ulonglong2 b01 = Bd[tx];
            ulonglong2 b23 = Bd[16 + tx];
            unsigned long long a2[8] = {a01.x, a01.y, a23.x, a23.y,
                                        a45.x, a45.y, a67.x, a67.y};
            unsigned long long b2[4] = {b01.x, b01.y, b23.x, b23.y};
#pragma unroll
            for (int i = 0; i < 8; ++i)
#pragma unroll
                for (int p = 0; p < 4; ++p) fma2(c2[i][p], a2[i], b2[p]);
        }
        __syncthreads();
    }

    // Epilogue: dist = ||e||^2 - 2*dot, per-row argmin -> packed atomicMin
#pragma unroll
    for (int i = 0; i < 8; ++i) {
        int lrow = (i < 4) ? (4 * ty + i) : (64 + 4 * ty + (i - 4));
        unsigned long long best = 0xFFFFFFFFFFFFFFFFull;
#pragma unroll
        for (int p = 0; p < 4; ++p) {
            int c0 = (p < 2) ? (4 * tx + 2 * p) : (64 + 4 * tx + 2 * (p - 2));
            float2 v = unpack2(c2[i][p]);
            float dd0 = en_s[c0] - 2.0f * v.x;
            float dd1 = en_s[c0 + 1] - 2.0f * v.y;
            unsigned long long e0 =
                ((unsigned long long)ford(dd0) << 32) | (unsigned)(ct * 128 + c0);
            unsigned long long e1 =
                ((unsigned long long)ford(dd1) << 32) | (unsigned)(ct * 128 + c0 + 1);
            best = umin64(best, umin64(e0, e1));
        }
        // reduce across the 16 lanes sharing this row (tx = 0..15 within half-warp)
#pragma unroll
        for (int o = 8; o > 0; o >>= 1) {
            unsigned long long other = __shfl_xor_sync(0xffffffffu, best, o);
            best = umin64(best, other);
        }
        if (tx == 0) atomicMin(&g_best[rt * 128 + lrow], best);
    }
}

// ---------------- kernel 4: gather + write (x_q | z_e | z_q) ----------------
__global__ void gather_kernel(const float* __restrict__ X,
                              const float* __restrict__ E,
                              float* __restrict__ out) {
    const int row = blockIdx.x;
    const int t = threadIdx.x;  // 128 threads, one float4 each (D=512)
    const int k = (int)(g_best[row] & 0xFFFFFFFFull);
    const float4 x = ((const float4*)(X + (size_t)row * DDIM))[t];
    const float4 e = ((const float4*)(E + (size_t)k * DDIM))[t];
    float4 xq;  // x_q = z_e + (z_q - z_e), computed as written (fp32 rounding)
    xq.x = x.x + (e.x - x.x);
    xq.y = x.y + (e.y - x.y);
    xq.z = x.z + (e.z - x.z);
    xq.w = x.w + (e.w - x.w);
    const size_t nd4 = (size_t)NROWS * (DDIM / 4);
    float4* o = (float4*)out;
    const size_t base = (size_t)row * (DDIM / 4) + t;
    o[base] = xq;              // x_q
    o[nd4 + base] = x;         // z_e
    o[2 * nd4 + base] = e;     // z_q
}

extern "C" void kernel_launch(void* const* d_in, const int* in_sizes, int n_in,
                              void* d_out, int out_size) {
    const float* X = (const float*)d_in[0];   // x [N, D] fp32
    const float* E = (const float*)d_in[1];   // embeddings [K, D] fp32
    float* out = (float*)d_out;               // [x_q | z_e | z_q], 3*N*D fp32

    init_best_kernel<<<NROWS / 256, 256>>>();
    enorm_kernel<<<(KEMB * 32) / 256, 256>>>(E);
    dim3 grid(KEMB / 128, NROWS / 128);       // x = col tile so B stays hot in L2
    vq_gemm_argmin<<<grid, 256>>>(X, E);
    gather_kernel<<<NROWS, 128>>>(X, E, out);
}

// round 4
// speedup vs baseline: 1.8194x; 1.8194x over previous
#include <cuda_runtime.h>
#include <cuda_fp16.h>
#include <cstdint>

#define NROWS 32768
#define KEMB  8192
#define DDIM  512

#define MT 128
#define NT 128
#define KC 64
#define NCHUNK (DDIM / KC)      // 8
#define NSTAGE 3
#define STAGE_BYTES 32768       // A 16K + B 16K
#define OFF_B 16384
#define SM_EN (NSTAGE * STAGE_BYTES)
#define SMEM_TOTAL (SM_EN + 512)
#define EPS_RESCUE 8e-3f
#define CAP_CAND 8192

// ---------------- device scratch ----------------
__device__ unsigned long long g_best[NROWS];   // packed (ford(dist), idx)
__device__ unsigned int g_second[NROWS];       // ford(dist) of runner-up
__device__ float g_enorm[KEMB];
__device__ int g_cand[CAP_CAND];
__device__ int g_cand_cnt;
__device__ __align__(128) __half g_Xh[NROWS * DDIM];
__device__ __align__(128) __half g_Eh[KEMB * DDIM];

// ---------------- helpers ----------------
__device__ __forceinline__ unsigned int ford(float f) {
    unsigned int u = __float_as_uint(f);
    return (u & 0x80000000u) ? ~u : (u | 0x80000000u);
}
__device__ __forceinline__ float unford(unsigned int u) {
    return (u & 0x80000000u) ? __uint_as_float(u ^ 0x80000000u)
                             : __uint_as_float(~u);
}
__device__ __forceinline__ uint32_t swz(uint32_t x) { return x ^ ((x >> 3) & 0x70); }
__device__ __forceinline__ uint32_t smem_u32(const void* p) {
    uint32_t a;
    asm("{ .reg .u64 t; cvta.to.shared.u64 t, %1; cvt.u32.u64 %0, t; }" : "=r"(a) : "l"(p));
    return a;
}
__device__ __forceinline__ void ldsm4(uint32_t* r, uint32_t addr) {
    asm volatile("ldmatrix.sync.aligned.m8n8.x4.shared.b16 {%0,%1,%2,%3}, [%4];"
                 : "=r"(r[0]), "=r"(r[1]), "=r"(r[2]), "=r"(r[3]) : "r"(addr));
}
__device__ __forceinline__ void mma16816(float* c, const uint32_t* a, uint32_t b0,
                                         uint32_t b1) {
    asm volatile(
        "mma.sync.aligned.m16n8k16.row.col.f32.f16.f16.f32 "
        "{%0,%1,%2,%3}, {%4,%5,%6,%7}, {%8,%9}, {%0,%1,%2,%3};"
        : "+f"(c[0]), "+f"(c[1]), "+f"(c[2]), "+f"(c[3])
        : "r"(a[0]), "r"(a[1]), "r"(a[2]), "r"(a[3]), "r"(b0), "r"(b1));
}
__device__ __forceinline__ void cpasync16(uint32_t so, const void* g) {
    asm volatile("cp.async.cg.shared.global [%0], [%1], 16;" :: "r"(so), "l"(g)
                 : "memory");
}

// ---------------- kernel: fp32 -> fp16 ----------------
__global__ void convert_f16_kernel(const float* __restrict__ src,
                                   __half* __restrict__ dst, int n4) {
    int i = blockIdx.x * blockDim.x + threadIdx.x;
    if (i >= n4) return;
    float4 v = ((const float4*)src)[i];
    __half2 h0 = __floats2half2_rn(v.x, v.y);
    __half2 h1 = __floats2half2_rn(v.z, v.w);
    ((uint2*)dst)[i] = make_uint2(*(uint32_t*)&h0, *(uint32_t*)&h1);
}

// ---------------- kernel: init ----------------
__global__ void init_kernel() {
    int i = blockIdx.x * blockDim.x + threadIdx.x;
    if (i < NROWS) {
        g_best[i] = 0xFFFFFFFFFFFFFFFFull;
        g_second[i] = 0xFFFFFFFFu;
    }
    if (i == 0) g_cand_cnt = 0;
}

// ---------------- kernel: ||e_k||^2 (exact fp32) ----------------
__global__ void enorm_kernel(const float* __restrict__ E) {
    int w = (blockIdx.x * blockDim.x + threadIdx.x) >> 5;
    int lane = threadIdx.x & 31;
    if (w >= KEMB) return;
    const float4* row = (const float4*)(E + (size_t)w * DDIM);
    float s = 0.f;
#pragma unroll
    for (int i = 0; i < 4; ++i) {
        float4 v = row[lane + 32 * i];
        s += v.x * v.x + v.y * v.y + v.z * v.z + v.w * v.w;
    }
#pragma unroll
    for (int o = 16; o > 0; o >>= 1) s += __shfl_xor_sync(0xffffffffu, s, o);
    if (lane == 0) g_enorm[w] = s;
}

// ---------------- fill one (A,B) k-chunk into a smem stage ----------------
__device__ __forceinline__ void fill_chunk(uint32_t sbase, int c, int rt, int ct) {
    const int tid = threadIdx.x;
#pragma unroll
    for (int i = 0; i < 4; ++i) {
        int ua = tid + i * 256;           // A: 1024 x 16B units
        int r = ua >> 3, u8 = ua & 7;
        const __half* g = g_Xh + ((size_t)(rt * MT + r)) * DDIM + c * KC + u8 * 8;
        cpasync16(sbase + swz(r * 128 + u8 * 16), g);
    }
#pragma unroll
    for (int i = 0; i < 4; ++i) {
        int ub = tid + i * 256;           // B: 1024 x 16B units
        int r = ub >> 3, u8 = ub & 7;
        const __half* g = g_Eh + ((size_t)(ct * NT + r)) * DDIM + c * KC + u8 * 8;
        cpasync16(sbase + OFF_B + swz(r * 128 + u8 * 16), g);
    }
    asm volatile("cp.async.commit_group;" ::: "memory");
}

// ---------------- kernel: fp16 HMMA GEMM + fused top-2 argmin ----------------
__global__ __launch_bounds__(256) void vq_mma_kernel() {
    extern __shared__ __align__(1024) char smem[];
    const uint32_t sb = smem_u32(smem);
    const int tid = threadIdx.x;
    const int lane = tid & 31;
    const int wid = tid >> 5;
    const int wm = wid & 1;      // 2 warp rows (64 M each)
    const int wn = wid >> 1;     // 4 warp cols (32 N each)
    const int ct = blockIdx.x;   // 0..63 code tiles
    const int rt = blockIdx.y;   // 0..255 row tiles

    if (tid < 128) ((float*)(smem + SM_EN))[tid] = g_enorm[ct * NT + tid];

    float acc[4][4][4];
#pragma unroll
    for (int mt = 0; mt < 4; ++mt)
#pragma unroll
        for (int nt = 0; nt < 4; ++nt)
#pragma unroll
            for (int j = 0; j < 4; ++j) acc[mt][nt][j] = 0.f;

    fill_chunk(sb + 0 * STAGE_BYTES, 0, rt, ct);
    fill_chunk(sb + 1 * STAGE_BYTES, 1, rt, ct);

    // ldmatrix per-lane address components
    const uint32_t a_row = (lane & 15);
    const uint32_t a_k16 = (lane >> 4);            // 0/1 -> +16B
    const uint32_t b_row = (lane & 7) + ((lane >> 4) & 1) * 8;
    const uint32_t b_k16 = (lane >> 3) & 1;

    for (int c = 0; c < NCHUNK; ++c) {
        if (c < NCHUNK - 2) asm volatile("cp.async.wait_group 1;" ::: "memory");
        else                asm volatile("cp.async.wait_group 0;" ::: "memory");
        __syncthreads();
        if (c + 2 < NCHUNK) fill_chunk(sb + ((c + 2) % NSTAGE) * STAGE_BYTES, c + 2, rt, ct);

        const uint32_t As = sb + (c % NSTAGE) * STAGE_BYTES;
        const uint32_t Bs = As + OFF_B;
#pragma unroll
        for (int ks = 0; ks < 4; ++ks) {
            uint32_t a[4][4], b[2][4];
#pragma unroll
            for (int mt = 0; mt < 4; ++mt)
                ldsm4(a[mt], As + swz((wm * 64 + mt * 16 + a_row) * 128 +
                                      ks * 32 + a_k16 * 16));
#pragma unroll
            for (int bt = 0; bt < 2; ++bt)
                ldsm4(b[bt], Bs + swz((wn * 32 + bt * 16 + b_row) * 128 +
                                      ks * 32 + b_k16 * 16));
#pragma unroll
            for (int mt = 0; mt < 4; ++mt)
#pragma unroll
                for (int nt = 0; nt < 4; ++nt)
                    mma16816(acc[mt][nt], a[mt], b[nt >> 1][(nt & 1) * 2],
                             b[nt >> 1][(nt & 1) * 2 + 1]);
        }
        __syncthreads();
    }

    // ---------------- epilogue: dist + per-row top-2 -> atomics ----------------
    const float* ens = (const float*)(smem + SM_EN);
#pragma unroll
    for (int mt = 0; mt < 4; ++mt) {
#pragma unroll
        for (int half = 0; half < 2; ++half) {
            unsigned long long b1 = 0xFFFFFFFFFFFFFFFFull;
            unsigned int s2 = 0xFFFFFFFFu;
#pragma unroll
            for (int nt = 0; nt < 4; ++nt) {
                int col = wn * 32 + nt * 8 + (lane & 3) * 2;
                float d0 = fmaf(-2.0f, acc[mt][nt][half * 2 + 0], ens[col]);
                float d1 = fmaf(-2.0f, acc[mt][nt][half * 2 + 1], ens[col + 1]);
                unsigned long long e0 =
                    ((unsigned long long)ford(d0) << 32) | (unsigned)(ct * NT + col);
                unsigned long long e1 =
                    ((unsigned long long)ford(d1) << 32) | (unsigned)(ct * NT + col + 1);
                if (e0 < b1) { s2 = min(s2, (unsigned)(b1 >> 32)); b1 = e0; }
                else s2 = min(s2, (unsigned)(e0 >> 32));
                if (e1 < b1) { s2 = min(s2, (unsigned)(b1 >> 32)); b1 = e1; }
                else s2 = min(s2, (unsigned)(e1 >> 32));
            }
#pragma unroll
            for (int o = 1; o <= 2; o <<= 1) {
                unsigned long long p = __shfl_xor_sync(0xffffffffu, b1, o);
                unsigned int t = __shfl_xor_sync(0xffffffffu, s2, o);
                if (p < b1) { s2 = min(min(s2, t), (unsigned)(b1 >> 32)); b1 = p; }
                else s2 = min(min(s2, t), (unsigned)(p >> 32));
            }
            if ((lane & 3) == 0) {
                int row = rt * MT + wm * 64 + mt * 16 + half * 8 + (lane >> 2);
                unsigned long long old = atomicMin(&g_best[row], b1);
                unsigned w = (b1 < old) ? (unsigned)(old >> 32) : (unsigned)(b1 >> 32);
                atomicMin(&g_second[row], min(w, s2));
            }
        }
    }
}

// ---------------- kernel: flag near-tie rows ----------------
__global__ void flag_kernel() {
    int row = blockIdx.x * blockDim.x + threadIdx.x;
    if (row >= NROWS) return;
    float f1 = unford((unsigned)(g_best[row] >> 32));
    float f2 = unford(g_second[row]);
    if (!(f2 - f1 >= EPS_RESCUE)) {
        int p = atomicAdd(&g_cand_cnt, 1);
        if (p < CAP_CAND) g_cand[p] = row;
    }
}

// ---------------- kernel: exact fp32 rescue for flagged rows ----------------
__global__ __launch_bounds__(256) void rescue_kernel(const float* __restrict__ X,
                                                     const float* __restrict__ E) {
    __shared__ float4 xs[128];
    __shared__ unsigned long long red[256];
    int cnt = g_cand_cnt;
    if (cnt > CAP_CAND) cnt = CAP_CAND;
    for (int ci = blockIdx.x; ci < cnt; ci += gridDim.x) {
        const int row = g_cand[ci];
        if (threadIdx.x < 128)
            xs[threadIdx.x] = ((const float4*)(X + (size_t)row * DDIM))[threadIdx.x];
        __syncthreads();
        unsigned long long best = 0xFFFFFFFFFFFFFFFFull;
        for (int k = threadIdx.x; k < KEMB; k += 256) {
            const float4* e4 = (const float4*)(E + (size_t)k * DDIM);
            float s = 0.f;
#pragma unroll 16
            for (int i = 0; i < 128; ++i) {
                float4 ev = e4[i], xv = xs[i];
                s = fmaf(ev.x, xv.x, s);
                s = fmaf(ev.y, xv.y, s);
                s = fmaf(ev.z, xv.z, s);
                s = fmaf(ev.w, xv.w, s);
            }
            float d = fmaf(-2.0f, s, g_enorm[k]);
            unsigned long long pk = ((unsigned long long)ford(d) << 32) | (unsigned)k;
            if (pk < best) best = pk;
        }
        red[threadIdx.x] = best;
        __syncthreads();
        for (int o = 128; o > 0; o >>= 1) {
            if (threadIdx.x < o && red[threadIdx.x + o] < red[threadIdx.x])
                red[threadIdx.x] = red[threadIdx.x + o];
            __syncthreads();
        }
        if (threadIdx.x == 0) g_best[row] = red[0];
        __syncthreads();
    }
}

// ---------------- kernel: gather + write (x_q | z_e | z_q) ----------------
__global__ void gather_kernel(const float* __restrict__ X,
                              const float* __restrict__ E,
                              float* __restrict__ out) {
    const int row = blockIdx.x;
    const int t = threadIdx.x;
    const int k = (int)(g_best[row] & 0xFFFFFFFFull);
    const float4 x = ((const float4*)(X + (size_t)row * DDIM))[t];
    const float4 e = ((const float4*)(E + (size_t)k * DDIM))[t];
    float4 xq;
    xq.x = x.x + (e.x - x.x);
    xq.y = x.y + (e.y - x.y);
    xq.z = x.z + (e.z - x.z);
    xq.w = x.w + (e.w - x.w);
    const size_t nd4 = (size_t)NROWS * (DDIM / 4);
    float4* o = (float4*)out;
    const size_t base = (size_t)row * (DDIM / 4) + t;
    o[base] = xq;
    o[nd4 + base] = x;
    o[2 * nd4 + base] = e;
}

extern "C" void kernel_launch(void* const* d_in, const int* in_sizes, int n_in,
                              void* d_out, int out_size) {
    const float* X = (const float*)d_in[0];
    const float* E = (const float*)d_in[1];
    float* out = (float*)d_out;

    cudaFuncSetAttribute(vq_mma_kernel, cudaFuncAttributeMaxDynamicSharedMemorySize,
                         SMEM_TOTAL);

    __half *xh, *eh;
    cudaGetSymbolAddress((void**)&xh, g_Xh);
    cudaGetSymbolAddress((void**)&eh, g_Eh);

    convert_f16_kernel<<<(NROWS * DDIM / 4) / 256, 256>>>(X, xh, NROWS * DDIM / 4);
    convert_f16_kernel<<<(KEMB * DDIM / 4) / 256, 256>>>(E, eh, KEMB * DDIM / 4);
    init_kernel<<<NROWS / 256, 256>>>();
    enorm_kernel<<<(KEMB * 32) / 256, 256>>>(E);
    dim3 grid(KEMB / NT, NROWS / MT);  // (64, 256)
    vq_mma_kernel<<<grid, 256, SMEM_TOTAL>>>();
    flag_kernel<<<NROWS / 256, 256>>>();
    rescue_kernel<<<512, 256>>>(X, E);
    gather_kernel<<<NROWS, 128>>>(X, E, out);
}